// round 1
// baseline (speedup 1.0000x reference)
#include <cuda_runtime.h>

#define BATCH 512
#define SEQLEN 512
#define INSZ 64
#define RES 1024
#define OUTSZ 64
#define ALPHA_F 0.5f

// Ping-pong state buffers (2 x 2 MB). Static __device__ storage: allowed.
__device__ float g_state[2][BATCH * RES];

__global__ void zero_state_kernel() {
    int i = blockIdx.x * blockDim.x + threadIdx.x;
    if (i < BATCH * RES) g_state[0][i] = 0.0f;
}

// ---------------------------------------------------------------------------
// Per-timestep fused kernel:
//   Snew = (1-a)*S + a*tanh( S @ W_res  +  x_t @ W_in )
// GEMM tiling: BM=BN=64, BK=16, 256 threads, 4x4 microtile per thread.
// Grid = (RES/64, BATCH/64) = (16, 8) = 128 CTAs.
// ---------------------------------------------------------------------------
#define BM 64
#define BN 64
#define BK 16
#define TM 4
#define TN 4

__global__ __launch_bounds__(256) void step_kernel(
    const float* __restrict__ input,   // [BATCH, SEQLEN, INSZ]
    const float* __restrict__ Wres,    // [RES, RES]
    const float* __restrict__ Win,     // [INSZ, RES]
    int t)
{
    const float* __restrict__ S    = g_state[t & 1];
    float*       __restrict__ Snew = g_state[(t + 1) & 1];

    __shared__ float As[BK][BM];   // A stored transposed: As[k][row]
    __shared__ float Bs[BK][BN];

    const int tid = threadIdx.x;
    const int tx  = tid & 15;       // 0..15 -> column group
    const int ty  = tid >> 4;       // 0..15 -> row group
    const int rowBase = blockIdx.y * BM;   // batch rows
    const int colBase = blockIdx.x * BN;   // reservoir cols

    // A-tile load mapping (64x16 tile, one float4 per thread, stored transposed)
    const int la = tid * 4;
    const int ar = la >> 4;        // row in tile (0..63)
    const int ac = la & 15;        // col in tile (0,4,8,12)
    // B-tile load mapping (16x64 tile, one float4 per thread)
    const int br = tid >> 4;       // row in tile (0..15)
    const int bc = (tid & 15) * 4; // col in tile

    float acc[TM][TN];
    #pragma unroll
    for (int i = 0; i < TM; i++)
        #pragma unroll
        for (int j = 0; j < TN; j++)
            acc[i][j] = 0.0f;

    // ---- Phase 1: K over RES  (S @ W_res) ----
    for (int k0 = 0; k0 < RES; k0 += BK) {
        float4 av = *reinterpret_cast<const float4*>(&S[(rowBase + ar) * RES + k0 + ac]);
        As[ac + 0][ar] = av.x;
        As[ac + 1][ar] = av.y;
        As[ac + 2][ar] = av.z;
        As[ac + 3][ar] = av.w;
        float4 bv = *reinterpret_cast<const float4*>(&Wres[(k0 + br) * RES + colBase + bc]);
        *reinterpret_cast<float4*>(&Bs[br][bc]) = bv;
        __syncthreads();

        #pragma unroll
        for (int k = 0; k < BK; k++) {
            float4 a4 = *reinterpret_cast<const float4*>(&As[k][ty * TM]);
            float4 b4 = *reinterpret_cast<const float4*>(&Bs[k][tx * TN]);
            float a[TM] = {a4.x, a4.y, a4.z, a4.w};
            float b[TN] = {b4.x, b4.y, b4.z, b4.w};
            #pragma unroll
            for (int i = 0; i < TM; i++)
                #pragma unroll
                for (int j = 0; j < TN; j++)
                    acc[i][j] += a[i] * b[j];
        }
        __syncthreads();
    }

    // ---- Phase 2: K over INSZ  (x_t @ W_in), fused input projection ----
    for (int k0 = 0; k0 < INSZ; k0 += BK) {
        float4 av = *reinterpret_cast<const float4*>(
            &input[((size_t)(rowBase + ar) * SEQLEN + t) * INSZ + k0 + ac]);
        As[ac + 0][ar] = av.x;
        As[ac + 1][ar] = av.y;
        As[ac + 2][ar] = av.z;
        As[ac + 3][ar] = av.w;
        float4 bv = *reinterpret_cast<const float4*>(&Win[(k0 + br) * RES + colBase + bc]);
        *reinterpret_cast<float4*>(&Bs[br][bc]) = bv;
        __syncthreads();

        #pragma unroll
        for (int k = 0; k < BK; k++) {
            float4 a4 = *reinterpret_cast<const float4*>(&As[k][ty * TM]);
            float4 b4 = *reinterpret_cast<const float4*>(&Bs[k][tx * TN]);
            float a[TM] = {a4.x, a4.y, a4.z, a4.w};
            float b[TN] = {b4.x, b4.y, b4.z, b4.w};
            #pragma unroll
            for (int i = 0; i < TM; i++)
                #pragma unroll
                for (int j = 0; j < TN; j++)
                    acc[i][j] += a[i] * b[j];
        }
        __syncthreads();
    }

    // ---- Epilogue: leaky tanh update ----
    #pragma unroll
    for (int i = 0; i < TM; i++) {
        const int row = rowBase + ty * TM + i;
        const int col = colBase + tx * TN;
        float4 sv = *reinterpret_cast<const float4*>(&S[row * RES + col]);
        float4 o;
        o.x = (1.0f - ALPHA_F) * sv.x + ALPHA_F * tanhf(acc[i][0]);
        o.y = (1.0f - ALPHA_F) * sv.y + ALPHA_F * tanhf(acc[i][1]);
        o.z = (1.0f - ALPHA_F) * sv.z + ALPHA_F * tanhf(acc[i][2]);
        o.w = (1.0f - ALPHA_F) * sv.w + ALPHA_F * tanhf(acc[i][3]);
        *reinterpret_cast<float4*>(&Snew[row * RES + col]) = o;
    }
}

// ---------------------------------------------------------------------------
// Output GEMM: out[512,64] = S_final[512,1024] @ W_out[1024,64]
// One block per batch row; 64 threads each own one output column.
// ---------------------------------------------------------------------------
__global__ __launch_bounds__(64) void output_kernel(
    const float* __restrict__ Wout,    // [RES, OUTSZ]
    float* __restrict__ out)           // [BATCH, OUTSZ]
{
    __shared__ float srow[RES];
    // After SEQLEN steps the final state sits in buffer (SEQLEN & 1) == 0.
    const float* __restrict__ S = g_state[SEQLEN & 1];
    const int b = blockIdx.x;
    const int j = threadIdx.x;

    for (int k = j; k < RES; k += 64)
        srow[k] = S[b * RES + k];
    __syncthreads();

    float sum = 0.0f;
    #pragma unroll 8
    for (int k = 0; k < RES; k++)
        sum = fmaf(srow[k], Wout[k * OUTSZ + j], sum);
    out[b * OUTSZ + j] = sum;
}

extern "C" void kernel_launch(void* const* d_in, const int* in_sizes, int n_in,
                              void* d_out, int out_size) {
    const float* input = (const float*)d_in[0];   // [512,512,64]
    const float* Wres  = (const float*)d_in[1];   // [1024,1024]
    const float* Win   = (const float*)d_in[2];   // [64,1024]
    const float* Wout  = (const float*)d_in[3];   // [1024,64]
    float* out = (float*)d_out;

    zero_state_kernel<<<(BATCH * RES + 255) / 256, 256>>>();

    dim3 grid(RES / BN, BATCH / BM);   // (16, 8) = 128 CTAs
    for (int t = 0; t < SEQLEN; t++)
        step_kernel<<<grid, 256>>>(input, Wres, Win, t);

    output_kernel<<<BATCH, 64>>>(Wout, out);
}

// round 2
// speedup vs baseline: 1.9769x; 1.9769x over previous
#include <cuda_runtime.h>
#include <cuda_bf16.h>
#include <cstdint>

#define BATCH 512
#define SEQLEN 512
#define INSZ 64
#define RES 1024
#define OUTSZ 64

// ---------------- static device buffers (no allocation allowed) -------------
__device__ float g_state[BATCH * RES];                       // fp32 state, in-place
__device__ __nv_bfloat16 g_shi[2][BATCH * RES];              // state hi, ping-pong
__device__ __nv_bfloat16 g_slo[2][BATCH * RES];              // state lo, ping-pong
__device__ __nv_bfloat16 g_whi[RES * RES];
__device__ __nv_bfloat16 g_wlo[RES * RES];
__device__ __nv_bfloat16 g_winhi[INSZ * RES];
__device__ __nv_bfloat16 g_winlo[INSZ * RES];
__device__ __nv_bfloat16 g_xhi[BATCH * SEQLEN * INSZ];
__device__ __nv_bfloat16 g_xlo[BATCH * SEQLEN * INSZ];

// ---------------- prep kernels ---------------------------------------------
__global__ void split_kernel(const float* __restrict__ src,
                             __nv_bfloat16* __restrict__ hi,
                             __nv_bfloat16* __restrict__ lo, int n) {
    int i = blockIdx.x * blockDim.x + threadIdx.x;
    int stride = gridDim.x * blockDim.x;
    for (; i < n; i += stride) {
        float v = src[i];
        __nv_bfloat16 h = __float2bfloat16(v);
        hi[i] = h;
        lo[i] = __float2bfloat16(v - __bfloat162float(h));
    }
}

__global__ void zero_kernel() {
    int i = blockIdx.x * blockDim.x + threadIdx.x;
    int stride = gridDim.x * blockDim.x;
    const __nv_bfloat16 z = __float2bfloat16(0.0f);
    for (int k = i; k < BATCH * RES; k += stride) {
        g_state[k] = 0.0f;
        g_shi[0][k] = z;
        g_slo[0][k] = z;
    }
}

// ---------------- step kernel ----------------------------------------------
// Snew = 0.5*S + 0.5*tanh( [Shi|Slo|Shi|xhi|xlo|xhi] @ [Whi;Whi;Wlo;WinHi;WinHi;WinLo] )
// GEMM: M=512, N=1024, K=3264.  BM=BN=64, BK=64, 128 threads (4 warps, 2x2),
// warp tile 32x32 via mma.sync.m16n8k16 bf16. 4-stage cp.async pipeline.
#define NIT 51                 // 48 main (3 x 16) + 3 input segments
#define STAGES 4
#define STAGE_BYTES 16384      // A 8KB + B 8KB

__device__ __forceinline__ uint32_t sw_off(int row, int colByte) {
    // 128B rows, XOR-swizzled 16B chunks: conflict-free cp.async + ldmatrix
    return (uint32_t)(row * 128 + ((((colByte >> 4) ^ (row & 7)) << 4) | (colByte & 15)));
}

__global__ __launch_bounds__(128) void step_kernel(int t) {
    extern __shared__ char smem[];
    const int tid  = threadIdx.x;
    const int lane = tid & 31;
    const int warp = tid >> 5;
    const int warpM = warp & 1;     // 2 warps along M
    const int warpN = warp >> 1;    // 2 warps along N
    const int rowBase = blockIdx.y * 64;   // batch rows
    const int colBase = blockIdx.x * 64;   // reservoir cols
    const int pp = t & 1;

    const uint32_t smem_u32 = (uint32_t)__cvta_generic_to_shared(smem);

    auto seg_ptrs = [&](int kk, const __nv_bfloat16*& A, long long& ldA,
                        const __nv_bfloat16*& B) {
        if (kk < 48) {
            int s  = kk >> 4;           // 0:Shi*Whi 1:Slo*Whi 2:Shi*Wlo
            int k0 = (kk & 15) << 6;    // 0..960
            A = (s == 1 ? g_slo[pp] : g_shi[pp]) + k0;
            ldA = RES;
            B = (s == 2 ? g_wlo : g_whi) + (long long)k0 * RES;
        } else {
            int s = kk - 48;            // 0:xhi*WinHi 1:xlo*WinHi 2:xhi*WinLo
            A = (s == 1 ? g_xlo : g_xhi) + (long long)t * INSZ;
            ldA = (long long)SEQLEN * INSZ;
            B = (s == 2 ? g_winlo : g_winhi);
        }
    };

    auto issue = [&](int kk) {
        const __nv_bfloat16 *A, *B;
        long long ldA;
        seg_ptrs(kk, A, ldA, B);
        uint32_t sa = smem_u32 + (kk & 3) * STAGE_BYTES;
        uint32_t sb = sa + 8192;
        #pragma unroll
        for (int i = 0; i < 4; i++) {          // A tile: 64x64 bf16, 512 x 16B chunks
            int c = tid + i * 128;
            int r = c >> 3, kc = c & 7;
            const void* gA = (const void*)(A + (long long)(rowBase + r) * ldA + kc * 8);
            uint32_t dA = sa + sw_off(r, kc * 16);
            asm volatile("cp.async.cg.shared.global [%0], [%1], 16;\n" :: "r"(dA), "l"(gA));
        }
        #pragma unroll
        for (int i = 0; i < 4; i++) {          // B tile: 64x64
            int c = tid + i * 128;
            int kr = c >> 3, nc = c & 7;
            const void* gB = (const void*)(B + (long long)kr * RES + colBase + nc * 8);
            uint32_t dB = sb + sw_off(kr, nc * 16);
            asm volatile("cp.async.cg.shared.global [%0], [%1], 16;\n" :: "r"(dB), "l"(gB));
        }
    };

    float acc[2][4][4];
    #pragma unroll
    for (int mf = 0; mf < 2; mf++)
        #pragma unroll
        for (int j = 0; j < 4; j++)
            #pragma unroll
            for (int r = 0; r < 4; r++) acc[mf][j][r] = 0.0f;

    // prologue: 3 stages in flight
    issue(0); asm volatile("cp.async.commit_group;\n" ::);
    issue(1); asm volatile("cp.async.commit_group;\n" ::);
    issue(2); asm volatile("cp.async.commit_group;\n" ::);

    for (int kk = 0; kk < NIT; kk++) {
        asm volatile("cp.async.wait_group %0;\n" :: "n"(2));
        __syncthreads();
        if (kk + 3 < NIT) issue(kk + 3);
        asm volatile("cp.async.commit_group;\n" ::);

        uint32_t sa = smem_u32 + (kk & 3) * STAGE_BYTES;
        uint32_t sb = sa + 8192;

        #pragma unroll
        for (int kf = 0; kf < 4; kf++) {       // 4 x k16 per BK=64
            uint32_t a[2][4];
            #pragma unroll
            for (int mf = 0; mf < 2; mf++) {
                int row = warpM * 32 + mf * 16 + (lane & 15);
                int colByte = kf * 32 + (lane >> 4) * 16;
                uint32_t addr = sa + sw_off(row, colByte);
                asm volatile("ldmatrix.sync.aligned.m8n8.x4.shared.b16 {%0,%1,%2,%3}, [%4];"
                    : "=r"(a[mf][0]), "=r"(a[mf][1]), "=r"(a[mf][2]), "=r"(a[mf][3])
                    : "r"(addr));
            }
            uint32_t b[2][4];
            #pragma unroll
            for (int nh = 0; nh < 2; nh++) {   // two n16 halves of warp's 32 cols
                int krow = kf * 16 + (lane & 7) + ((lane >> 3) & 1) * 8;
                int colByte = (warpN * 32 + nh * 16 + (lane >> 4) * 8) * 2;
                uint32_t addr = sb + sw_off(krow, colByte);
                asm volatile("ldmatrix.sync.aligned.m8n8.x4.trans.shared.b16 {%0,%1,%2,%3}, [%4];"
                    : "=r"(b[nh][0]), "=r"(b[nh][1]), "=r"(b[nh][2]), "=r"(b[nh][3])
                    : "r"(addr));
            }
            #pragma unroll
            for (int mf = 0; mf < 2; mf++)
                #pragma unroll
                for (int j = 0; j < 4; j++) {
                    uint32_t b0 = b[j >> 1][(j & 1) * 2];
                    uint32_t b1 = b[j >> 1][(j & 1) * 2 + 1];
                    asm volatile(
                        "mma.sync.aligned.m16n8k16.row.col.f32.bf16.bf16.f32 "
                        "{%0,%1,%2,%3}, {%4,%5,%6,%7}, {%8,%9}, {%0,%1,%2,%3};"
                        : "+f"(acc[mf][j][0]), "+f"(acc[mf][j][1]),
                          "+f"(acc[mf][j][2]), "+f"(acc[mf][j][3])
                        : "r"(a[mf][0]), "r"(a[mf][1]), "r"(a[mf][2]), "r"(a[mf][3]),
                          "r"(b0), "r"(b1));
                }
        }
    }

    // ---- epilogue: leaky tanh; update fp32 state in place (tile-exclusive),
    //      emit bf16 hi/lo for next step into ping-pong buffers ----
    __nv_bfloat16* __restrict__ shiN = g_shi[pp ^ 1];
    __nv_bfloat16* __restrict__ sloN = g_slo[pp ^ 1];
    #pragma unroll
    for (int mf = 0; mf < 2; mf++)
        #pragma unroll
        for (int j = 0; j < 4; j++)
            #pragma unroll
            for (int h = 0; h < 2; h++) {
                int row = rowBase + warpM * 32 + mf * 16 + (lane >> 2) + 8 * h;
                int col = colBase + warpN * 32 + j * 8 + (lane & 3) * 2;
                long long idx = (long long)row * RES + col;
                float2 sold = *reinterpret_cast<float2*>(&g_state[idx]);
                float n0 = 0.5f * sold.x + 0.5f * tanhf(acc[mf][j][h * 2 + 0]);
                float n1 = 0.5f * sold.y + 0.5f * tanhf(acc[mf][j][h * 2 + 1]);
                *reinterpret_cast<float2*>(&g_state[idx]) = make_float2(n0, n1);
                __nv_bfloat16 h0 = __float2bfloat16(n0);
                __nv_bfloat16 h1 = __float2bfloat16(n1);
                __nv_bfloat162 hv; hv.x = h0; hv.y = h1;
                __nv_bfloat162 lv;
                lv.x = __float2bfloat16(n0 - __bfloat162float(h0));
                lv.y = __float2bfloat16(n1 - __bfloat162float(h1));
                *reinterpret_cast<__nv_bfloat162*>(&shiN[idx]) = hv;
                *reinterpret_cast<__nv_bfloat162*>(&sloN[idx]) = lv;
            }
}

// ---------------- output GEMM ----------------------------------------------
__global__ __launch_bounds__(64) void output_kernel(
    const float* __restrict__ Wout, float* __restrict__ out) {
    __shared__ float srow[RES];
    const int b = blockIdx.x;
    const int j = threadIdx.x;
    for (int k = j; k < RES; k += 64) srow[k] = g_state[b * RES + k];
    __syncthreads();
    float sum = 0.0f;
    #pragma unroll 8
    for (int k = 0; k < RES; k++)
        sum = fmaf(srow[k], Wout[k * OUTSZ + j], sum);
    out[b * OUTSZ + j] = sum;
}

// ---------------- launch ----------------------------------------------------
extern "C" void kernel_launch(void* const* d_in, const int* in_sizes, int n_in,
                              void* d_out, int out_size) {
    const float* input = (const float*)d_in[0];   // [512,512,64]
    const float* Wres  = (const float*)d_in[1];   // [1024,1024]
    const float* Win   = (const float*)d_in[2];   // [64,1024]
    const float* Wout  = (const float*)d_in[3];   // [1024,64]
    float* out = (float*)d_out;

    void *whi, *wlo, *winhi, *winlo, *xhi, *xlo;
    cudaGetSymbolAddress(&whi,   g_whi);
    cudaGetSymbolAddress(&wlo,   g_wlo);
    cudaGetSymbolAddress(&winhi, g_winhi);
    cudaGetSymbolAddress(&winlo, g_winlo);
    cudaGetSymbolAddress(&xhi,   g_xhi);
    cudaGetSymbolAddress(&xlo,   g_xlo);

    cudaFuncSetAttribute(step_kernel,
                         cudaFuncAttributeMaxDynamicSharedMemorySize,
                         STAGES * STAGE_BYTES);

    split_kernel<<<2048, 256>>>(Wres, (__nv_bfloat16*)whi, (__nv_bfloat16*)wlo, RES * RES);
    split_kernel<<<256, 256>>>(Win, (__nv_bfloat16*)winhi, (__nv_bfloat16*)winlo, INSZ * RES);
    split_kernel<<<8192, 256>>>(input, (__nv_bfloat16*)xhi, (__nv_bfloat16*)xlo,
                                BATCH * SEQLEN * INSZ);
    zero_kernel<<<1024, 512>>>();

    dim3 grid(RES / 64, BATCH / 64);   // (16, 8) = 128 CTAs
    for (int t = 0; t < SEQLEN; t++)
        step_kernel<<<grid, 128, STAGES * STAGE_BYTES>>>(t);

    output_kernel<<<BATCH, 64>>>(Wout, out);
}

// round 3
// speedup vs baseline: 2.2042x; 1.1150x over previous
#include <cuda_runtime.h>
#include <cuda_bf16.h>
#include <cstdint>

#define BATCH 512
#define SEQLEN 512
#define INSZ 64
#define RES 1024
#define OUTSZ 64

// ---------------- static device buffers (no allocation allowed) -------------
__device__ float g_state[BATCH * RES];                       // fp32 state, in-place
__device__ __nv_bfloat16 g_shi[2][BATCH * RES];              // state hi, ping-pong
__device__ __nv_bfloat16 g_slo[2][BATCH * RES];              // state lo, ping-pong
__device__ __nv_bfloat16 g_whi[RES * RES];
__device__ __nv_bfloat16 g_wlo[RES * RES];
__device__ __nv_bfloat16 g_winhi[INSZ * RES];
__device__ __nv_bfloat16 g_winlo[INSZ * RES];
__device__ __nv_bfloat16 g_xhi[BATCH * SEQLEN * INSZ];
__device__ __nv_bfloat16 g_xlo[BATCH * SEQLEN * INSZ];

// ---------------- prep kernels ---------------------------------------------
__global__ void split_kernel(const float* __restrict__ src,
                             __nv_bfloat16* __restrict__ hi,
                             __nv_bfloat16* __restrict__ lo, int n) {
    int i = blockIdx.x * blockDim.x + threadIdx.x;
    int stride = gridDim.x * blockDim.x;
    for (; i < n; i += stride) {
        float v = src[i];
        __nv_bfloat16 h = __float2bfloat16(v);
        hi[i] = h;
        lo[i] = __float2bfloat16(v - __bfloat162float(h));
    }
}

__global__ void zero_kernel() {
    int i = blockIdx.x * blockDim.x + threadIdx.x;
    int stride = gridDim.x * blockDim.x;
    const __nv_bfloat16 z = __float2bfloat16(0.0f);
    for (int k = i; k < BATCH * RES; k += stride) {
        g_state[k] = 0.0f;
        g_shi[0][k] = z;
        g_slo[0][k] = z;
    }
}

// ---------------- step kernel ----------------------------------------------
// Snew = 0.5*S + 0.5*tanh( [Shi|Slo|Shi|xhi|xlo|xhi] @ [Whi;Whi;Wlo;WinHi;WinHi;WinLo] )
// GEMM: M=512, N=1024, K=3264.  BM=BN=64, BK=64, 256 threads (8 warps, 4Mx2N),
// warp tile 16x32 via mma.sync.m16n8k16 bf16. 4-stage cp.async pipeline.
// 2 warps per SMSP -> latency hiding for ldmatrix/mma chains.
#define NIT 51                 // 48 main (3 x 16) + 3 input segments
#define STAGES 4
#define STAGE_BYTES 16384      // A 8KB + B 8KB

__device__ __forceinline__ uint32_t sw_off(int row, int colByte) {
    // 128B rows, XOR-swizzled 16B chunks: conflict-free cp.async + ldmatrix
    return (uint32_t)(row * 128 + ((((colByte >> 4) ^ (row & 7)) << 4) | (colByte & 15)));
}

__global__ __launch_bounds__(256) void step_kernel(int t) {
    extern __shared__ char smem[];
    const int tid  = threadIdx.x;
    const int lane = tid & 31;
    const int warp = tid >> 5;
    const int warpM = warp & 3;     // 4 warps along M (16 rows each)
    const int warpN = warp >> 2;    // 2 warps along N (32 cols each)
    const int rowBase = blockIdx.y * 64;   // batch rows
    const int colBase = blockIdx.x * 64;   // reservoir cols
    const int pp = t & 1;

    const uint32_t smem_u32 = (uint32_t)__cvta_generic_to_shared(smem);

    auto seg_ptrs = [&](int kk, const __nv_bfloat16*& A, long long& ldA,
                        const __nv_bfloat16*& B) {
        if (kk < 48) {
            int s  = kk >> 4;           // 0:Shi*Whi 1:Slo*Whi 2:Shi*Wlo
            int k0 = (kk & 15) << 6;    // 0..960
            A = (s == 1 ? g_slo[pp] : g_shi[pp]) + k0;
            ldA = RES;
            B = (s == 2 ? g_wlo : g_whi) + (long long)k0 * RES;
        } else {
            int s = kk - 48;            // 0:xhi*WinHi 1:xlo*WinHi 2:xhi*WinLo
            A = (s == 1 ? g_xlo : g_xhi) + (long long)t * INSZ;
            ldA = (long long)SEQLEN * INSZ;
            B = (s == 2 ? g_winlo : g_winhi);
        }
    };

    auto issue = [&](int kk) {
        const __nv_bfloat16 *A, *B;
        long long ldA;
        seg_ptrs(kk, A, ldA, B);
        uint32_t sa = smem_u32 + (kk & 3) * STAGE_BYTES;
        uint32_t sb = sa + 8192;
        #pragma unroll
        for (int i = 0; i < 2; i++) {          // A tile: 64x64 bf16, 512 x 16B chunks
            int c = tid + i * 256;
            int r = c >> 3, kc = c & 7;
            const void* gA = (const void*)(A + (long long)(rowBase + r) * ldA + kc * 8);
            uint32_t dA = sa + sw_off(r, kc * 16);
            asm volatile("cp.async.cg.shared.global [%0], [%1], 16;\n" :: "r"(dA), "l"(gA));
        }
        #pragma unroll
        for (int i = 0; i < 2; i++) {          // B tile: 64x64
            int c = tid + i * 256;
            int kr = c >> 3, nc = c & 7;
            const void* gB = (const void*)(B + (long long)kr * RES + colBase + nc * 8);
            uint32_t dB = sb + sw_off(kr, nc * 16);
            asm volatile("cp.async.cg.shared.global [%0], [%1], 16;\n" :: "r"(dB), "l"(gB));
        }
    };

    float acc[4][4];                 // 4 n8 groups x 4 regs (warp tile 16x32)
    #pragma unroll
    for (int j = 0; j < 4; j++)
        #pragma unroll
        for (int r = 0; r < 4; r++) acc[j][r] = 0.0f;

    // prologue: 3 stages in flight
    issue(0); asm volatile("cp.async.commit_group;\n" ::);
    issue(1); asm volatile("cp.async.commit_group;\n" ::);
    issue(2); asm volatile("cp.async.commit_group;\n" ::);

    for (int kk = 0; kk < NIT; kk++) {
        asm volatile("cp.async.wait_group %0;\n" :: "n"(2));
        __syncthreads();
        if (kk + 3 < NIT) issue(kk + 3);
        asm volatile("cp.async.commit_group;\n" ::);

        uint32_t sa = smem_u32 + (kk & 3) * STAGE_BYTES;
        uint32_t sb = sa + 8192;

        #pragma unroll
        for (int kf = 0; kf < 4; kf++) {       // 4 x k16 per BK=64
            uint32_t a[4];
            {
                int row = warpM * 16 + (lane & 15);
                int colByte = kf * 32 + (lane >> 4) * 16;
                uint32_t addr = sa + sw_off(row, colByte);
                asm volatile("ldmatrix.sync.aligned.m8n8.x4.shared.b16 {%0,%1,%2,%3}, [%4];"
                    : "=r"(a[0]), "=r"(a[1]), "=r"(a[2]), "=r"(a[3])
                    : "r"(addr));
            }
            uint32_t b[2][4];
            #pragma unroll
            for (int nh = 0; nh < 2; nh++) {   // two n16 halves of warp's 32 cols
                int krow = kf * 16 + (lane & 7) + ((lane >> 3) & 1) * 8;
                int colByte = (warpN * 32 + nh * 16 + (lane >> 4) * 8) * 2;
                uint32_t addr = sb + sw_off(krow, colByte);
                asm volatile("ldmatrix.sync.aligned.m8n8.x4.trans.shared.b16 {%0,%1,%2,%3}, [%4];"
                    : "=r"(b[nh][0]), "=r"(b[nh][1]), "=r"(b[nh][2]), "=r"(b[nh][3])
                    : "r"(addr));
            }
            #pragma unroll
            for (int j = 0; j < 4; j++) {
                uint32_t b0 = b[j >> 1][(j & 1) * 2];
                uint32_t b1 = b[j >> 1][(j & 1) * 2 + 1];
                asm volatile(
                    "mma.sync.aligned.m16n8k16.row.col.f32.bf16.bf16.f32 "
                    "{%0,%1,%2,%3}, {%4,%5,%6,%7}, {%8,%9}, {%0,%1,%2,%3};"
                    : "+f"(acc[j][0]), "+f"(acc[j][1]),
                      "+f"(acc[j][2]), "+f"(acc[j][3])
                    : "r"(a[0]), "r"(a[1]), "r"(a[2]), "r"(a[3]),
                      "r"(b0), "r"(b1));
            }
        }
    }

    // ---- epilogue: leaky tanh; update fp32 state in place (tile-exclusive),
    //      emit bf16 hi/lo for next step into ping-pong buffers ----
    __nv_bfloat16* __restrict__ shiN = g_shi[pp ^ 1];
    __nv_bfloat16* __restrict__ sloN = g_slo[pp ^ 1];
    #pragma unroll
    for (int j = 0; j < 4; j++)
        #pragma unroll
        for (int h = 0; h < 2; h++) {
            int row = rowBase + warpM * 16 + (lane >> 2) + 8 * h;
            int col = colBase + warpN * 32 + j * 8 + (lane & 3) * 2;
            long long idx = (long long)row * RES + col;
            float2 sold = *reinterpret_cast<float2*>(&g_state[idx]);
            float n0 = 0.5f * sold.x + 0.5f * tanhf(acc[j][h * 2 + 0]);
            float n1 = 0.5f * sold.y + 0.5f * tanhf(acc[j][h * 2 + 1]);
            *reinterpret_cast<float2*>(&g_state[idx]) = make_float2(n0, n1);
            __nv_bfloat16 h0 = __float2bfloat16(n0);
            __nv_bfloat16 h1 = __float2bfloat16(n1);
            __nv_bfloat162 hv; hv.x = h0; hv.y = h1;
            __nv_bfloat162 lv;
            lv.x = __float2bfloat16(n0 - __bfloat162float(h0));
            lv.y = __float2bfloat16(n1 - __bfloat162float(h1));
            *reinterpret_cast<__nv_bfloat162*>(&shiN[idx]) = hv;
            *reinterpret_cast<__nv_bfloat162*>(&sloN[idx]) = lv;
        }
}

// ---------------- output GEMM ----------------------------------------------
__global__ __launch_bounds__(64) void output_kernel(
    const float* __restrict__ Wout, float* __restrict__ out) {
    __shared__ float srow[RES];
    const int b = blockIdx.x;
    const int j = threadIdx.x;
    for (int k = j; k < RES; k += 64) srow[k] = g_state[b * RES + k];
    __syncthreads();
    float sum = 0.0f;
    #pragma unroll 8
    for (int k = 0; k < RES; k++)
        sum = fmaf(srow[k], Wout[k * OUTSZ + j], sum);
    out[b * OUTSZ + j] = sum;
}

// ---------------- launch ----------------------------------------------------
extern "C" void kernel_launch(void* const* d_in, const int* in_sizes, int n_in,
                              void* d_out, int out_size) {
    const float* input = (const float*)d_in[0];   // [512,512,64]
    const float* Wres  = (const float*)d_in[1];   // [1024,1024]
    const float* Win   = (const float*)d_in[2];   // [64,1024]
    const float* Wout  = (const float*)d_in[3];   // [1024,64]
    float* out = (float*)d_out;

    void *whi, *wlo, *winhi, *winlo, *xhi, *xlo;
    cudaGetSymbolAddress(&whi,   g_whi);
    cudaGetSymbolAddress(&wlo,   g_wlo);
    cudaGetSymbolAddress(&winhi, g_winhi);
    cudaGetSymbolAddress(&winlo, g_winlo);
    cudaGetSymbolAddress(&xhi,   g_xhi);
    cudaGetSymbolAddress(&xlo,   g_xlo);

    cudaFuncSetAttribute(step_kernel,
                         cudaFuncAttributeMaxDynamicSharedMemorySize,
                         STAGES * STAGE_BYTES);

    split_kernel<<<2048, 256>>>(Wres, (__nv_bfloat16*)whi, (__nv_bfloat16*)wlo, RES * RES);
    split_kernel<<<256, 256>>>(Win, (__nv_bfloat16*)winhi, (__nv_bfloat16*)winlo, INSZ * RES);
    split_kernel<<<8192, 256>>>(input, (__nv_bfloat16*)xhi, (__nv_bfloat16*)xlo,
                                BATCH * SEQLEN * INSZ);
    zero_kernel<<<1024, 512>>>();

    dim3 grid(RES / 64, BATCH / 64);   // (16, 8) = 128 CTAs
    for (int t = 0; t < SEQLEN; t++)
        step_kernel<<<grid, 256, STAGES * STAGE_BYTES>>>(t);

    output_kernel<<<BATCH, 64>>>(Wout, out);
}

// round 4
// speedup vs baseline: 3.5679x; 1.6187x over previous
#include <cuda_runtime.h>
#include <cuda_bf16.h>
#include <cstdint>

#define BATCH 512
#define SEQLEN 512
#define INSZ 64
#define RES 1024
#define OUTSZ 64

// ---------------- static device buffers (no allocation allowed) -------------
__device__ float g_state[BATCH * RES];                       // fp32 state, in-place
__device__ __nv_bfloat16 g_shi[2][BATCH * RES];              // state hi, ping-pong
__device__ __nv_bfloat16 g_slo[2][BATCH * RES];              // state lo, ping-pong
__device__ __nv_bfloat16 g_whi[RES * RES];
__device__ __nv_bfloat16 g_wlo[RES * RES];
__device__ __nv_bfloat16 g_winhi[INSZ * RES];
__device__ __nv_bfloat16 g_winlo[INSZ * RES];
__device__ __nv_bfloat16 g_xhi[BATCH * SEQLEN * INSZ];
__device__ __nv_bfloat16 g_xlo[BATCH * SEQLEN * INSZ];

// ---------------- prep kernels ---------------------------------------------
__global__ void split_kernel(const float* __restrict__ src,
                             __nv_bfloat16* __restrict__ hi,
                             __nv_bfloat16* __restrict__ lo, int n) {
    int i = blockIdx.x * blockDim.x + threadIdx.x;
    int stride = gridDim.x * blockDim.x;
    for (; i < n; i += stride) {
        float v = src[i];
        __nv_bfloat16 h = __float2bfloat16(v);
        hi[i] = h;
        lo[i] = __float2bfloat16(v - __bfloat162float(h));
    }
}

__global__ void zero_kernel() {
    int i = blockIdx.x * blockDim.x + threadIdx.x;
    int stride = gridDim.x * blockDim.x;
    const __nv_bfloat16 z = __float2bfloat16(0.0f);
    for (int k = i; k < BATCH * RES; k += stride) {
        g_state[k] = 0.0f;
        g_shi[0][k] = z;
        g_slo[0][k] = z;
    }
}

// ---------------- step kernel ----------------------------------------------
// Y = Shi@Whi + Slo@Whi + Shi@Wlo (+ same for input proj), fused per K-block:
// each BK=64 iteration loads Ahi/Alo/Bhi/Blo tiles ONCE and runs all 3
// products into one accumulator. 17 iterations (16 main + 1 input).
// BM=BN=64, 256 threads (8 warps, 4Mx2N), warp tile 16x32, 4-stage pipeline.
#define NIT 17
#define STAGES 4
#define STAGE_BYTES 32768      // Ahi 8K | Alo 8K | Bhi 8K | Blo 8K

__device__ __forceinline__ uint32_t sw_off(int row, int colByte) {
    // 128B rows, XOR-swizzled 16B chunks: conflict-free cp.async + ldmatrix
    return (uint32_t)(row * 128 + ((((colByte >> 4) ^ (row & 7)) << 4) | (colByte & 15)));
}

__global__ __launch_bounds__(256) void step_kernel(int t) {
    extern __shared__ char smem[];
    const int tid  = threadIdx.x;
    const int lane = tid & 31;
    const int warp = tid >> 5;
    const int warpM = warp & 3;     // 4 warps along M (16 rows each)
    const int warpN = warp >> 2;    // 2 warps along N (32 cols each)
    const int rowBase = blockIdx.y * 64;   // batch rows
    const int colBase = blockIdx.x * 64;   // reservoir cols
    const int pp = t & 1;

    const uint32_t smem_u32 = (uint32_t)__cvta_generic_to_shared(smem);

    // issue all four tiles of one K-block into stage (kk & 3)
    auto issue = [&](int kk) {
        const __nv_bfloat16 *Ahi, *Alo, *Bhi, *Blo;
        long long ldA;
        if (kk < 16) {
            int k0 = kk << 6;
            Ahi = g_shi[pp] + k0;
            Alo = g_slo[pp] + k0;
            ldA = RES;
            Bhi = g_whi + (long long)k0 * RES;
            Blo = g_wlo + (long long)k0 * RES;
        } else {
            Ahi = g_xhi + (long long)t * INSZ;
            Alo = g_xlo + (long long)t * INSZ;
            ldA = (long long)SEQLEN * INSZ;
            Bhi = g_winhi;
            Blo = g_winlo;
        }
        uint32_t base = smem_u32 + (kk & 3) * STAGE_BYTES;
        // A tiles: 64x64 bf16 = 512 x 16B chunks each, 2 chunks/thread/tile
        #pragma unroll
        for (int i = 0; i < 2; i++) {
            int c = tid + i * 256;
            int r = c >> 3, kc = c & 7;
            long long aoff = (long long)(rowBase + r) * ldA + kc * 8;
            uint32_t so = sw_off(r, kc * 16);
            asm volatile("cp.async.cg.shared.global [%0], [%1], 16;\n"
                         :: "r"(base + so), "l"((const void*)(Ahi + aoff)));
            asm volatile("cp.async.cg.shared.global [%0], [%1], 16;\n"
                         :: "r"(base + 8192 + so), "l"((const void*)(Alo + aoff)));
        }
        // B tiles
        #pragma unroll
        for (int i = 0; i < 2; i++) {
            int c = tid + i * 256;
            int kr = c >> 3, nc = c & 7;
            long long boff = (long long)kr * RES + colBase + nc * 8;
            uint32_t so = sw_off(kr, nc * 16);
            asm volatile("cp.async.cg.shared.global [%0], [%1], 16;\n"
                         :: "r"(base + 16384 + so), "l"((const void*)(Bhi + boff)));
            asm volatile("cp.async.cg.shared.global [%0], [%1], 16;\n"
                         :: "r"(base + 24576 + so), "l"((const void*)(Blo + boff)));
        }
    };

    float acc[4][4];                 // warp tile 16x32: 4 n8 groups x 4 regs
    #pragma unroll
    for (int j = 0; j < 4; j++)
        #pragma unroll
        for (int r = 0; r < 4; r++) acc[j][r] = 0.0f;

    issue(0); asm volatile("cp.async.commit_group;\n" ::);
    issue(1); asm volatile("cp.async.commit_group;\n" ::);
    issue(2); asm volatile("cp.async.commit_group;\n" ::);

    for (int kk = 0; kk < NIT; kk++) {
        asm volatile("cp.async.wait_group %0;\n" :: "n"(2));
        __syncthreads();
        if (kk + 3 < NIT) issue(kk + 3);
        asm volatile("cp.async.commit_group;\n" ::);

        uint32_t base = smem_u32 + (kk & 3) * STAGE_BYTES;

        #pragma unroll
        for (int kf = 0; kf < 4; kf++) {       // 4 x k16 per BK=64
            // A fragments (hi & lo) for this warp's 16 rows
            uint32_t ahi[4], alo[4];
            {
                int row = warpM * 16 + (lane & 15);
                int colByte = kf * 32 + (lane >> 4) * 16;
                uint32_t so = sw_off(row, colByte);
                asm volatile("ldmatrix.sync.aligned.m8n8.x4.shared.b16 {%0,%1,%2,%3}, [%4];"
                    : "=r"(ahi[0]), "=r"(ahi[1]), "=r"(ahi[2]), "=r"(ahi[3])
                    : "r"(base + so));
                asm volatile("ldmatrix.sync.aligned.m8n8.x4.shared.b16 {%0,%1,%2,%3}, [%4];"
                    : "=r"(alo[0]), "=r"(alo[1]), "=r"(alo[2]), "=r"(alo[3])
                    : "r"(base + 8192 + so));
            }
            // B fragments (hi & lo), two n16 halves of warp's 32 cols
            uint32_t bhi[2][4], blo[2][4];
            #pragma unroll
            for (int nh = 0; nh < 2; nh++) {
                int krow = kf * 16 + (lane & 7) + ((lane >> 3) & 1) * 8;
                int colByte = (warpN * 32 + nh * 16 + (lane >> 4) * 8) * 2;
                uint32_t so = sw_off(krow, colByte);
                asm volatile("ldmatrix.sync.aligned.m8n8.x4.trans.shared.b16 {%0,%1,%2,%3}, [%4];"
                    : "=r"(bhi[nh][0]), "=r"(bhi[nh][1]), "=r"(bhi[nh][2]), "=r"(bhi[nh][3])
                    : "r"(base + 16384 + so));
                asm volatile("ldmatrix.sync.aligned.m8n8.x4.trans.shared.b16 {%0,%1,%2,%3}, [%4];"
                    : "=r"(blo[nh][0]), "=r"(blo[nh][1]), "=r"(blo[nh][2]), "=r"(blo[nh][3])
                    : "r"(base + 24576 + so));
            }
            // 3 products into the same accumulator
            #pragma unroll
            for (int j = 0; j < 4; j++) {
                uint32_t bh0 = bhi[j >> 1][(j & 1) * 2], bh1 = bhi[j >> 1][(j & 1) * 2 + 1];
                uint32_t bl0 = blo[j >> 1][(j & 1) * 2], bl1 = blo[j >> 1][(j & 1) * 2 + 1];
                asm volatile(
                    "mma.sync.aligned.m16n8k16.row.col.f32.bf16.bf16.f32 "
                    "{%0,%1,%2,%3}, {%4,%5,%6,%7}, {%8,%9}, {%0,%1,%2,%3};"
                    : "+f"(acc[j][0]), "+f"(acc[j][1]), "+f"(acc[j][2]), "+f"(acc[j][3])
                    : "r"(ahi[0]), "r"(ahi[1]), "r"(ahi[2]), "r"(ahi[3]), "r"(bh0), "r"(bh1));
                asm volatile(
                    "mma.sync.aligned.m16n8k16.row.col.f32.bf16.bf16.f32 "
                    "{%0,%1,%2,%3}, {%4,%5,%6,%7}, {%8,%9}, {%0,%1,%2,%3};"
                    : "+f"(acc[j][0]), "+f"(acc[j][1]), "+f"(acc[j][2]), "+f"(acc[j][3])
                    : "r"(alo[0]), "r"(alo[1]), "r"(alo[2]), "r"(alo[3]), "r"(bh0), "r"(bh1));
                asm volatile(
                    "mma.sync.aligned.m16n8k16.row.col.f32.bf16.bf16.f32 "
                    "{%0,%1,%2,%3}, {%4,%5,%6,%7}, {%8,%9}, {%0,%1,%2,%3};"
                    : "+f"(acc[j][0]), "+f"(acc[j][1]), "+f"(acc[j][2]), "+f"(acc[j][3])
                    : "r"(ahi[0]), "r"(ahi[1]), "r"(ahi[2]), "r"(ahi[3]), "r"(bl0), "r"(bl1));
            }
        }
    }

    // ---- epilogue: leaky tanh; update fp32 state in place (tile-exclusive),
    //      emit bf16 hi/lo for next step into ping-pong buffers ----
    __nv_bfloat16* __restrict__ shiN = g_shi[pp ^ 1];
    __nv_bfloat16* __restrict__ sloN = g_slo[pp ^ 1];
    #pragma unroll
    for (int j = 0; j < 4; j++)
        #pragma unroll
        for (int h = 0; h < 2; h++) {
            int row = rowBase + warpM * 16 + (lane >> 2) + 8 * h;
            int col = colBase + warpN * 32 + j * 8 + (lane & 3) * 2;
            long long idx = (long long)row * RES + col;
            float2 sold = *reinterpret_cast<float2*>(&g_state[idx]);
            float n0 = 0.5f * sold.x + 0.5f * tanhf(acc[j][h * 2 + 0]);
            float n1 = 0.5f * sold.y + 0.5f * tanhf(acc[j][h * 2 + 1]);
            *reinterpret_cast<float2*>(&g_state[idx]) = make_float2(n0, n1);
            __nv_bfloat16 h0 = __float2bfloat16(n0);
            __nv_bfloat16 h1 = __float2bfloat16(n1);
            __nv_bfloat162 hv; hv.x = h0; hv.y = h1;
            __nv_bfloat162 lv;
            lv.x = __float2bfloat16(n0 - __bfloat162float(h0));
            lv.y = __float2bfloat16(n1 - __bfloat162float(h1));
            *reinterpret_cast<__nv_bfloat162*>(&shiN[idx]) = hv;
            *reinterpret_cast<__nv_bfloat162*>(&sloN[idx]) = lv;
        }
}

// ---------------- output GEMM ----------------------------------------------
__global__ __launch_bounds__(64) void output_kernel(
    const float* __restrict__ Wout, float* __restrict__ out) {
    __shared__ float srow[RES];
    const int b = blockIdx.x;
    const int j = threadIdx.x;
    for (int k = j; k < RES; k += 64) srow[k] = g_state[b * RES + k];
    __syncthreads();
    float sum = 0.0f;
    #pragma unroll 8
    for (int k = 0; k < RES; k++)
        sum = fmaf(srow[k], Wout[k * OUTSZ + j], sum);
    out[b * OUTSZ + j] = sum;
}

// ---------------- launch ----------------------------------------------------
extern "C" void kernel_launch(void* const* d_in, const int* in_sizes, int n_in,
                              void* d_out, int out_size) {
    const float* input = (const float*)d_in[0];   // [512,512,64]
    const float* Wres  = (const float*)d_in[1];   // [1024,1024]
    const float* Win   = (const float*)d_in[2];   // [64,1024]
    const float* Wout  = (const float*)d_in[3];   // [1024,64]
    float* out = (float*)d_out;

    void *whi, *wlo, *winhi, *winlo, *xhi, *xlo;
    cudaGetSymbolAddress(&whi,   g_whi);
    cudaGetSymbolAddress(&wlo,   g_wlo);
    cudaGetSymbolAddress(&winhi, g_winhi);
    cudaGetSymbolAddress(&winlo, g_winlo);
    cudaGetSymbolAddress(&xhi,   g_xhi);
    cudaGetSymbolAddress(&xlo,   g_xlo);

    cudaFuncSetAttribute(step_kernel,
                         cudaFuncAttributeMaxDynamicSharedMemorySize,
                         STAGES * STAGE_BYTES);

    split_kernel<<<2048, 256>>>(Wres, (__nv_bfloat16*)whi, (__nv_bfloat16*)wlo, RES * RES);
    split_kernel<<<256, 256>>>(Win, (__nv_bfloat16*)winhi, (__nv_bfloat16*)winlo, INSZ * RES);
    split_kernel<<<8192, 256>>>(input, (__nv_bfloat16*)xhi, (__nv_bfloat16*)xlo,
                                BATCH * SEQLEN * INSZ);
    zero_kernel<<<1024, 512>>>();

    dim3 grid(RES / 64, BATCH / 64);   // (16, 8) = 128 CTAs
    for (int t = 0; t < SEQLEN; t++)
        step_kernel<<<grid, 256, STAGES * STAGE_BYTES>>>(t);

    output_kernel<<<BATCH, 64>>>(Wout, out);
}

// round 6
// speedup vs baseline: 4.0828x; 1.1443x over previous
#include <cuda_runtime.h>
#include <cuda_fp16.h>
#include <cstdint>

#define BATCH 512
#define SEQLEN 512
#define INSZ 64
#define RES 1024
#define OUTSZ 64

// ---------------- static device buffers (no allocation allowed) -------------
__device__ float g_state[BATCH * RES];              // fp32 state, in-place
__device__ __half g_shi[2][BATCH * RES];            // state hi (fp16), ping-pong
__device__ __half g_slo[2][BATCH * RES];            // state lo (fp16), ping-pong
__device__ __half g_w16[RES * RES];                 // W_res in fp16
__device__ __half g_win16[INSZ * RES];              // W_in in fp16
__device__ __half g_xhi[BATCH * SEQLEN * INSZ];     // input hi
__device__ __half g_xlo[BATCH * SEQLEN * INSZ];     // input lo

// ---------------- prep kernels ---------------------------------------------
__global__ void split_kernel(const float* __restrict__ src,
                             __half* __restrict__ hi,
                             __half* __restrict__ lo, int n) {
    int i = blockIdx.x * blockDim.x + threadIdx.x;
    int stride = gridDim.x * blockDim.x;
    for (; i < n; i += stride) {
        float v = src[i];
        __half h = __float2half(v);
        hi[i] = h;
        lo[i] = __float2half(v - __half2float(h));
    }
}

__global__ void cvt_kernel(const float* __restrict__ src,
                           __half* __restrict__ dst, int n) {
    int i = blockIdx.x * blockDim.x + threadIdx.x;
    int stride = gridDim.x * blockDim.x;
    for (; i < n; i += stride) dst[i] = __float2half(src[i]);
}

__global__ void zero_kernel() {
    int i = blockIdx.x * blockDim.x + threadIdx.x;
    int stride = gridDim.x * blockDim.x;
    const __half z = __float2half(0.0f);
    for (int k = i; k < BATCH * RES; k += stride) {
        g_state[k] = 0.0f;
        g_shi[0][k] = z;
        g_slo[0][k] = z;
    }
}

// ---------------- step kernel ----------------------------------------------
// Y = Shi@W16 + Slo@W16 (+ xhi@Win16 + xlo@Win16), fused per K-block:
// each BK=64 iteration loads Ahi/Alo/B tiles once, runs 2 products into one
// accumulator. 17 iterations (16 state/W + 1 input/Win).
// BM=BN=64, 256 threads (8 warps, 4Mx2N), warp tile 16x32, 4-stage pipeline.
#define NIT 17
#define STAGES 4
#define STAGE_BYTES 24576      // Ahi 8K | Alo 8K | B 8K
#define SA_LO 8192
#define SB    16384

__device__ __forceinline__ uint32_t sw_off(int row, int colByte) {
    // 128B rows, XOR-swizzled 16B chunks: conflict-free cp.async + ldmatrix
    return (uint32_t)(row * 128 + ((((colByte >> 4) ^ (row & 7)) << 4) | (colByte & 15)));
}

__global__ __launch_bounds__(256) void step_kernel(int t) {
    extern __shared__ char smem[];
    const int tid  = threadIdx.x;
    const int lane = tid & 31;
    const int warp = tid >> 5;
    const int warpM = warp & 3;     // 4 warps along M (16 rows each)
    const int warpN = warp >> 2;    // 2 warps along N (32 cols each)
    const int rowBase = blockIdx.y * 64;   // batch rows
    const int colBase = blockIdx.x * 64;   // reservoir cols
    const int pp = t & 1;

    const uint32_t smem_u32 = (uint32_t)__cvta_generic_to_shared(smem);

    // issue the three tiles of one K-block into stage (kk & 3)
    auto issue = [&](int kk) {
        const __half *Ahi, *Alo, *B;
        long long ldA;
        if (kk < 16) {
            int k0 = kk << 6;
            Ahi = g_shi[pp] + k0;
            Alo = g_slo[pp] + k0;
            ldA = RES;
            B = g_w16 + (long long)k0 * RES;
        } else {
            Ahi = g_xhi + (long long)t * INSZ;
            Alo = g_xlo + (long long)t * INSZ;
            ldA = (long long)SEQLEN * INSZ;
            B = g_win16;
        }
        uint32_t base = smem_u32 + (kk & 3) * STAGE_BYTES;
        // A tiles: 64x64 fp16 = 512 x 16B chunks each, 2 chunks/thread/tile
        #pragma unroll
        for (int i = 0; i < 2; i++) {
            int c = tid + i * 256;
            int r = c >> 3, kc = c & 7;
            long long aoff = (long long)(rowBase + r) * ldA + kc * 8;
            uint32_t so = sw_off(r, kc * 16);
            asm volatile("cp.async.cg.shared.global [%0], [%1], 16;\n"
                         :: "r"(base + so), "l"((const void*)(Ahi + aoff)));
            asm volatile("cp.async.cg.shared.global [%0], [%1], 16;\n"
                         :: "r"(base + SA_LO + so), "l"((const void*)(Alo + aoff)));
        }
        // B tile
        #pragma unroll
        for (int i = 0; i < 2; i++) {
            int c = tid + i * 256;
            int kr = c >> 3, nc = c & 7;
            long long boff = (long long)kr * RES + colBase + nc * 8;
            uint32_t so = sw_off(kr, nc * 16);
            asm volatile("cp.async.cg.shared.global [%0], [%1], 16;\n"
                         :: "r"(base + SB + so), "l"((const void*)(B + boff)));
        }
    };

    float acc[4][4];                 // warp tile 16x32: 4 n8 groups x 4 regs
    #pragma unroll
    for (int j = 0; j < 4; j++)
        #pragma unroll
        for (int r = 0; r < 4; r++) acc[j][r] = 0.0f;

    issue(0); asm volatile("cp.async.commit_group;\n" ::);
    issue(1); asm volatile("cp.async.commit_group;\n" ::);
    issue(2); asm volatile("cp.async.commit_group;\n" ::);

    for (int kk = 0; kk < NIT; kk++) {
        asm volatile("cp.async.wait_group %0;\n" :: "n"(2));
        __syncthreads();
        if (kk + 3 < NIT) issue(kk + 3);
        asm volatile("cp.async.commit_group;\n" ::);

        uint32_t base = smem_u32 + (kk & 3) * STAGE_BYTES;

        #pragma unroll
        for (int kf = 0; kf < 4; kf++) {       // 4 x k16 per BK=64
            // A fragments (hi & lo) for this warp's 16 rows
            uint32_t ahi[4], alo[4];
            {
                int row = warpM * 16 + (lane & 15);
                int colByte = kf * 32 + (lane >> 4) * 16;
                uint32_t so = sw_off(row, colByte);
                asm volatile("ldmatrix.sync.aligned.m8n8.x4.shared.b16 {%0,%1,%2,%3}, [%4];"
                    : "=r"(ahi[0]), "=r"(ahi[1]), "=r"(ahi[2]), "=r"(ahi[3])
                    : "r"(base + so));
                asm volatile("ldmatrix.sync.aligned.m8n8.x4.shared.b16 {%0,%1,%2,%3}, [%4];"
                    : "=r"(alo[0]), "=r"(alo[1]), "=r"(alo[2]), "=r"(alo[3])
                    : "r"(base + SA_LO + so));
            }
            // B fragments, two n16 halves of warp's 32 cols
            uint32_t b[2][4];
            #pragma unroll
            for (int nh = 0; nh < 2; nh++) {
                int krow = kf * 16 + (lane & 7) + ((lane >> 3) & 1) * 8;
                int colByte = (warpN * 32 + nh * 16 + (lane >> 4) * 8) * 2;
                uint32_t so = sw_off(krow, colByte);
                asm volatile("ldmatrix.sync.aligned.m8n8.x4.trans.shared.b16 {%0,%1,%2,%3}, [%4];"
                    : "=r"(b[nh][0]), "=r"(b[nh][1]), "=r"(b[nh][2]), "=r"(b[nh][3])
                    : "r"(base + SB + so));
            }
            // 2 products into the same accumulator
            #pragma unroll
            for (int j = 0; j < 4; j++) {
                uint32_t b0 = b[j >> 1][(j & 1) * 2], b1 = b[j >> 1][(j & 1) * 2 + 1];
                asm volatile(
                    "mma.sync.aligned.m16n8k16.row.col.f32.f16.f16.f32 "
                    "{%0,%1,%2,%3}, {%4,%5,%6,%7}, {%8,%9}, {%0,%1,%2,%3};"
                    : "+f"(acc[j][0]), "+f"(acc[j][1]), "+f"(acc[j][2]), "+f"(acc[j][3])
                    : "r"(ahi[0]), "r"(ahi[1]), "r"(ahi[2]), "r"(ahi[3]), "r"(b0), "r"(b1));
                asm volatile(
                    "mma.sync.aligned.m16n8k16.row.col.f32.f16.f16.f32 "
                    "{%0,%1,%2,%3}, {%4,%5,%6,%7}, {%8,%9}, {%0,%1,%2,%3};"
                    : "+f"(acc[j][0]), "+f"(acc[j][1]), "+f"(acc[j][2]), "+f"(acc[j][3])
                    : "r"(alo[0]), "r"(alo[1]), "r"(alo[2]), "r"(alo[3]), "r"(b0), "r"(b1));
            }
        }
    }

    // ---- epilogue: leaky tanh; update fp32 state in place (tile-exclusive),
    //      emit fp16 hi/lo for next step into ping-pong buffers ----
    __half* __restrict__ shiN = g_shi[pp ^ 1];
    __half* __restrict__ sloN = g_slo[pp ^ 1];
    #pragma unroll
    for (int j = 0; j < 4; j++)
        #pragma unroll
        for (int h = 0; h < 2; h++) {
            int row = rowBase + warpM * 16 + (lane >> 2) + 8 * h;
            int col = colBase + warpN * 32 + j * 8 + (lane & 3) * 2;
            long long idx = (long long)row * RES + col;
            float2 sold = *reinterpret_cast<float2*>(&g_state[idx]);
            float n0 = 0.5f * sold.x + 0.5f * tanhf(acc[j][h * 2 + 0]);
            float n1 = 0.5f * sold.y + 0.5f * tanhf(acc[j][h * 2 + 1]);
            *reinterpret_cast<float2*>(&g_state[idx]) = make_float2(n0, n1);
            __half h0 = __float2half(n0);
            __half h1 = __float2half(n1);
            __half2 hv; hv.x = h0; hv.y = h1;
            __half2 lv;
            lv.x = __float2half(n0 - __half2float(h0));
            lv.y = __float2half(n1 - __half2float(h1));
            *reinterpret_cast<__half2*>(&shiN[idx]) = hv;
            *reinterpret_cast<__half2*>(&sloN[idx]) = lv;
        }
}

// ---------------- output GEMM ----------------------------------------------
__global__ __launch_bounds__(64) void output_kernel(
    const float* __restrict__ Wout, float* __restrict__ out) {
    __shared__ float srow[RES];
    const int b = blockIdx.x;
    const int j = threadIdx.x;
    for (int k = j; k < RES; k += 64) srow[k] = g_state[b * RES + k];
    __syncthreads();
    float sum = 0.0f;
    #pragma unroll 8
    for (int k = 0; k < RES; k++)
        sum = fmaf(srow[k], Wout[k * OUTSZ + j], sum);
    out[b * OUTSZ + j] = sum;
}

// ---------------- launch ----------------------------------------------------
extern "C" void kernel_launch(void* const* d_in, const int* in_sizes, int n_in,
                              void* d_out, int out_size) {
    const float* input = (const float*)d_in[0];   // [512,512,64]
    const float* Wres  = (const float*)d_in[1];   // [1024,1024]
    const float* Win   = (const float*)d_in[2];   // [64,1024]
    const float* Wout  = (const float*)d_in[3];   // [1024,64]
    float* out = (float*)d_out;

    void *w16, *win16, *xhi, *xlo;
    cudaGetSymbolAddress(&w16,   g_w16);
    cudaGetSymbolAddress(&win16, g_win16);
    cudaGetSymbolAddress(&xhi,   g_xhi);
    cudaGetSymbolAddress(&xlo,   g_xlo);

    cudaFuncSetAttribute(step_kernel,
                         cudaFuncAttributeMaxDynamicSharedMemorySize,
                         STAGES * STAGE_BYTES);

    cvt_kernel<<<2048, 256>>>(Wres, (__half*)w16, RES * RES);
    cvt_kernel<<<256, 256>>>(Win, (__half*)win16, INSZ * RES);
    split_kernel<<<8192, 256>>>(input, (__half*)xhi, (__half*)xlo,
                                BATCH * SEQLEN * INSZ);
    zero_kernel<<<1024, 512>>>();

    dim3 grid(RES / 64, BATCH / 64);   // (16, 8) = 128 CTAs
    for (int t = 0; t < SEQLEN; t++)
        step_kernel<<<grid, 256, STAGES * STAGE_BYTES>>>(t);

    output_kernel<<<BATCH, 64>>>(Wout, out);
}